// round 8
// baseline (speedup 1.0000x reference)
#include <cuda_runtime.h>
#include <cuda_bf16.h>
#include <cuda_fp8.h>
#include <math.h>
#include <stdint.h>

#define N 8192
#define D 256
#define INVT (1.0f / 0.07f)
#define FSCALE 16.0f                     // features scaled by 16 before e4m3
#define ESC (INVT / (FSCALE * FSCALE))   // logit scale on raw scaled acc
#define NB 64                            // 8192/128 blocks per dim
#define NTILE (NB * (NB + 1) / 2)        // 2080 upper-triangular tiles

__device__ __align__(16) uint8_t g_f8[N * D];   // 2MB normalized e4m3 (x16)
__device__ float g_rowpart[NB * N];   // [cb][i]  2MB
__device__ float g_colpart[NB * N];   // [rb][j]  2MB
__device__ float g_posdot[N];         // raw scaled acc
__device__ float g_blk[128];
__device__ unsigned int g_cnt;
__device__ unsigned int g_ready[NB];  // slice-normalized flags

// smem: A chunks (2x16KB) @0, B chunks @32KB, reduce buffers after
#define SM_B    32768
#define SM_ROW  65536                 // float[128][2]  (1KB)
#define SM_COL  (65536 + 1024)        // float[128][4]  (2KB)
#define SMEM_TOTAL (65536 + 1024 + 2048)

// ---------------------------------------------------------------------------
__device__ __forceinline__ uint32_t smem_u32(const void* p) {
    uint32_t a;
    asm("{ .reg .u64 t; cvta.to.shared.u64 t, %1; cvt.u32.u64 %0, t; }" : "=r"(a) : "l"(p));
    return a;
}
#define SW128(o) ((o) ^ (((o) >> 3) & 0x70))

__device__ __forceinline__ void cpasync16(uint32_t s, const void* g) {
    asm volatile("cp.async.cg.shared.global [%0], [%1], 16;" :: "r"(s), "l"(g));
}
#define CP_COMMIT() asm volatile("cp.async.commit_group;" ::: "memory")
#define CP_WAIT(n)  asm volatile("cp.async.wait_group %0;" :: "n"(n) : "memory")

__device__ __forceinline__ void ldsm_x4(uint32_t& r0, uint32_t& r1, uint32_t& r2,
                                        uint32_t& r3, uint32_t a) {
    asm volatile("ldmatrix.sync.aligned.m8n8.x4.shared.b16 {%0,%1,%2,%3}, [%4];"
        : "=r"(r0), "=r"(r1), "=r"(r2), "=r"(r3) : "r"(a));
}
// fp8 e4m3 MMA, fp32 accumulate: D = A(16x32) * B(32x8) + D
__device__ __forceinline__ void mma16832(float* c, const uint32_t* a,
                                         uint32_t b0, uint32_t b1) {
    asm volatile(
        "mma.sync.aligned.m16n8k32.row.col.f32.e4m3.e4m3.f32 "
        "{%0,%1,%2,%3},{%4,%5,%6,%7},{%8,%9},{%0,%1,%2,%3};"
        : "+f"(c[0]), "+f"(c[1]), "+f"(c[2]), "+f"(c[3])
        : "r"(a[0]), "r"(a[1]), "r"(a[2]), "r"(a[3]), "r"(b0), "r"(b1));
}

__device__ __forceinline__ uint32_t ld_acq(const unsigned int* p) {
    uint32_t v;
    asm volatile("ld.global.acquire.gpu.b32 %0, [%1];" : "=r"(v) : "l"(p) : "memory");
    return v;
}
__device__ __forceinline__ void st_rel(unsigned int* p, uint32_t v) {
    asm volatile("st.global.release.gpu.b32 [%0], %1;" :: "l"(p), "r"(v) : "memory");
}

// ---------------------------------------------------------------------------
// Fused kernel: (bid < NB) normalize slice bid first; all CTAs then wait for
// their rb/cb slices, run FP8 MMA sim GEMM on upper-triangular tiles with
// double-buffered K chunks, fused exp epilogue, in-smem partial reduction.
// ---------------------------------------------------------------------------
__global__ __launch_bounds__(256, 2) void simlse_mma(const float* __restrict__ x) {
    extern __shared__ __align__(1024) char smem[];
    const uint32_t sA0 = smem_u32(smem);
    float* sm_row = (float*)(smem + SM_ROW);   // [128][2]
    float* sm_col = (float*)(smem + SM_COL);   // [128][4]

    // triangular tile map: bid 0..63 -> (0,0)..(0,63), so normalizer CTAs
    // (bid < NB) are exactly the first NB blocks (wave-1 resident).
    int t = blockIdx.x, rb = 0, base = 0;
    while (base + (NB - rb) <= t) { base += NB - rb; rb++; }
    const int cb = rb + (t - base);
    const bool diag = (rb == cb);

    const int tid  = threadIdx.x;
    const int lane = tid & 31;
    const int warp = tid >> 5;
    const int wm   = warp >> 1;
    const int wn   = warp & 1;
    const int i0   = rb * 128;
    const int j0   = cb * 128;

    // ---- phase 0: normalize (first NB CTAs only) ----
    if (blockIdx.x < NB) {
        const int slice = blockIdx.x;
        #pragma unroll
        for (int pass = 0; pass < 8; pass++) {
            const int row0 = slice * 128 + pass * 16 + warp * 2;
            const float* xr0 = x + (size_t)row0 * D + lane * 8;
            const float* xr1 = xr0 + D;
            float4 a0 = *(const float4*)xr0;
            float4 a1 = *(const float4*)(xr0 + 4);
            float4 b0 = *(const float4*)xr1;
            float4 b1 = *(const float4*)(xr1 + 4);

            float s0 = a0.x*a0.x + a0.y*a0.y + a0.z*a0.z + a0.w*a0.w +
                       a1.x*a1.x + a1.y*a1.y + a1.z*a1.z + a1.w*a1.w;
            float s1 = b0.x*b0.x + b0.y*b0.y + b0.z*b0.z + b0.w*b0.w +
                       b1.x*b1.x + b1.y*b1.y + b1.z*b1.z + b1.w*b1.w;
            #pragma unroll
            for (int o = 16; o > 0; o >>= 1) {
                s0 += __shfl_xor_sync(0xffffffffu, s0, o);
                s1 += __shfl_xor_sync(0xffffffffu, s1, o);
            }
            const float r0 = FSCALE / fmaxf(sqrtf(s0), 1e-8f);
            const float r1 = FSCALE / fmaxf(sqrtf(s1), 1e-8f);
            {
                __nv_fp8x4_e4m3 lo(make_float4(a0.x*r0, a0.y*r0, a0.z*r0, a0.w*r0));
                __nv_fp8x4_e4m3 hi(make_float4(a1.x*r0, a1.y*r0, a1.z*r0, a1.w*r0));
                uint2 pk; pk.x = (uint32_t)lo.__x; pk.y = (uint32_t)hi.__x;
                *(uint2*)(g_f8 + (size_t)row0 * D + lane * 8) = pk;
            }
            {
                __nv_fp8x4_e4m3 lo(make_float4(b0.x*r1, b0.y*r1, b0.z*r1, b0.w*r1));
                __nv_fp8x4_e4m3 hi(make_float4(b1.x*r1, b1.y*r1, b1.z*r1, b1.w*r1));
                uint2 pk; pk.x = (uint32_t)lo.__x; pk.y = (uint32_t)hi.__x;
                *(uint2*)(g_f8 + (size_t)(row0 + 1) * D + lane * 8) = pk;
            }
        }
        __threadfence();
        __syncthreads();
        if (tid == 0) st_rel(&g_ready[slice], 1u);
    }

    // ---- phase 1: wait for the two slices this tile needs ----
    if (tid == 0) {
        while (ld_acq(&g_ready[rb]) == 0u) __nanosleep(64);
        while (ld_acq(&g_ready[cb]) == 0u) __nanosleep(64);
    }
    __syncthreads();

    const int sel = lane >> 3;
    const int sub = lane & 7;
    const int g   = lane >> 2;
    const int q   = lane & 3;

    float c[2][8][4];
    #pragma unroll
    for (int mf = 0; mf < 2; mf++)
        #pragma unroll
        for (int nf = 0; nf < 8; nf++)
            #pragma unroll
            for (int e = 0; e < 4; e++) c[mf][nf][e] = 0.0f;

    // chunk loader: K-chunk kc (128B of K), 128 rows per matrix
    auto load_chunk = [&](int kc) {
        const uint8_t* gA = g_f8 + (size_t)i0 * D + kc * 128;
        const uint8_t* gB = g_f8 + (size_t)j0 * D + kc * 128;
        const uint32_t dA = sA0 + (kc << 14);
        const uint32_t dB = sA0 + SM_B + (kc << 14);
        #pragma unroll
        for (int v = 0; v < 4; v++) {
            int idx = tid + 256 * v;   // 0..1023
            int r   = idx >> 3;        // 0..127
            int ci  = idx & 7;         // 16B unit
            uint32_t so = SW128(r * 128 + ci * 16);
            cpasync16(dA + so, gA + (size_t)r * D + ci * 16);
            if (!diag) cpasync16(dB + so, gB + (size_t)r * D + ci * 16);
        }
    };

    load_chunk(0);
    CP_COMMIT();
    load_chunk(1);
    CP_COMMIT();

    const uint32_t sBbase = diag ? sA0 : (sA0 + SM_B);

    float rs[2][2] = {{0.0f, 0.0f}, {0.0f, 0.0f}};

    auto load_a = [&](uint32_t bA, int ks, uint32_t a[2][4]) {
        #pragma unroll
        for (int mf = 0; mf < 2; mf++) {
            int row = wm * 32 + mf * 16 + (sel & 1) * 8 + sub;
            uint32_t off = (uint32_t)(row * 128 + ks * 32 + (sel >> 1) * 16);
            ldsm_x4(a[mf][0], a[mf][1], a[mf][2], a[mf][3], bA + SW128(off));
        }
    };
    auto load_b = [&](uint32_t bB, int ks, uint32_t b[4][4]) {
        #pragma unroll
        for (int p = 0; p < 4; p++) {
            int n = wn * 64 + p * 16 + (sel >> 1) * 8 + sub;
            uint32_t off = (uint32_t)(n * 128 + ks * 32 + (sel & 1) * 16);
            ldsm_x4(b[p][0], b[p][1], b[p][2], b[p][3], bB + SW128(off));
        }
    };

    // ---- chunk 0: wait only for the first commit group ----
    CP_WAIT(1);
    __syncthreads();
    #pragma unroll
    for (int ks = 0; ks < 4; ks++) {
        uint32_t a[2][4], b[4][4];
        load_a(sA0, ks, a);
        load_b(sBbase, ks, b);
        #pragma unroll
        for (int p = 0; p < 4; p++)
            #pragma unroll
            for (int mf = 0; mf < 2; mf++) {
                mma16832(c[mf][2 * p],     a[mf], b[p][0], b[p][1]);
                mma16832(c[mf][2 * p + 1], a[mf], b[p][2], b[p][3]);
            }
    }

    // ---- chunk 1: ks 0-2 normal, ks 3 fused with epilogue ----
    CP_WAIT(0);
    __syncthreads();
    {
        const uint32_t bA = sA0 + 16384;
        const uint32_t bB = sBbase + 16384;

        #pragma unroll
        for (int ks = 0; ks < 3; ks++) {
            uint32_t a[2][4], b[4][4];
            load_a(bA, ks, a);
            load_b(bB, ks, b);
            #pragma unroll
            for (int p = 0; p < 4; p++)
                #pragma unroll
                for (int mf = 0; mf < 2; mf++) {
                    mma16832(c[mf][2 * p],     a[mf], b[p][0], b[p][1]);
                    mma16832(c[mf][2 * p + 1], a[mf], b[p][2], b[p][3]);
                }
        }

        // ks == 3: per nf, finish MMA then run that nf's epilogue immediately
        uint32_t a[2][4], b[4][4];
        load_a(bA, 3, a);
        load_b(bB, 3, b);
        #pragma unroll
        for (int p = 0; p < 4; p++) {
            #pragma unroll
            for (int half = 0; half < 2; half++) {
                const int nf = 2 * p + half;
                mma16832(c[0][nf], a[0], b[p][2 * half], b[p][2 * half + 1]);
                mma16832(c[1][nf], a[1], b[p][2 * half], b[p][2 * half + 1]);

                float s0 = 0.0f, s1 = 0.0f;
                const int jb = j0 + wn * 64 + nf * 8 + 2 * q;
                #pragma unroll
                for (int mf = 0; mf < 2; mf++) {
                    #pragma unroll
                    for (int h = 0; h < 2; h++) {
                        const int i  = i0 + wm * 32 + mf * 16 + 8 * h + g;
                        const int pc = (i + N / 2) & (N - 1);
                        const float v0 = c[mf][nf][h * 2 + 0];
                        const float v1 = c[mf][nf][h * 2 + 1];
                        if (jb == pc)     { g_posdot[i] = v0; g_posdot[jb] = v0; }
                        if (jb + 1 == pc) { g_posdot[i] = v1; g_posdot[jb + 1] = v1; }
                        const float e0 = (jb != i)     ? __expf(v0 * ESC) : 0.0f;
                        const float e1 = (jb + 1 != i) ? __expf(v1 * ESC) : 0.0f;
                        rs[mf][h] += e0 + e1;
                        s0 += e0;
                        s1 += e1;
                    }
                }
                s0 += __shfl_xor_sync(0xffffffffu, s0, 4);
                s0 += __shfl_xor_sync(0xffffffffu, s0, 8);
                s0 += __shfl_xor_sync(0xffffffffu, s0, 16);
                s1 += __shfl_xor_sync(0xffffffffu, s1, 4);
                s1 += __shfl_xor_sync(0xffffffffu, s1, 8);
                s1 += __shfl_xor_sync(0xffffffffu, s1, 16);
                if (g == nf) {
                    const int jl = wn * 64 + nf * 8 + 2 * q;
                    sm_col[jl * 4 + wm]       = s0;
                    sm_col[(jl + 1) * 4 + wm] = s1;
                }
            }
        }
    }

    // row partials: reduce over the 4 q-lanes, stash to smem
    #pragma unroll
    for (int mf = 0; mf < 2; mf++) {
        #pragma unroll
        for (int h = 0; h < 2; h++) {
            float v = rs[mf][h];
            v += __shfl_xor_sync(0xffffffffu, v, 1);
            v += __shfl_xor_sync(0xffffffffu, v, 2);
            if (q == 0) {
                const int il = wm * 32 + mf * 16 + 8 * h + g;
                sm_row[il * 2 + wn] = v;
            }
        }
    }
    __syncthreads();

    if (tid < 128) {
        g_rowpart[(size_t)cb * N + i0 + tid] = sm_row[tid * 2] + sm_row[tid * 2 + 1];
    } else if (!diag) {
        const int j = tid - 128;
        g_colpart[(size_t)rb * N + j0 + j] =
            sm_col[j * 4] + sm_col[j * 4 + 1] + sm_col[j * 4 + 2] + sm_col[j * 4 + 3];
    }
}

// ---------------------------------------------------------------------------
// Kernel 2: per-row nll. 128 blocks x 256 threads, 4 threads per row.
// Also resets g_ready flags for the next graph replay.
// ---------------------------------------------------------------------------
__global__ void finalize_kernel(float* __restrict__ out) {
    const int tid  = threadIdx.x;
    const int part = tid & 3;                      // 0..3
    const int i    = blockIdx.x * 64 + (tid >> 2); // row

    if (blockIdx.x == 0 && tid < NB) g_ready[tid] = 0u;

    const float* basep = (part < 2) ? g_rowpart : g_colpart;
    const int off = (part & 1) * 32;

    float s = 0.0f;
    #pragma unroll 8
    for (int k = 0; k < 32; k++) s += basep[(size_t)(off + k) * N + i];

    s += __shfl_xor_sync(0xffffffffu, s, 1);
    s += __shfl_xor_sync(0xffffffffu, s, 2);

    float local = (part == 0) ? (logf(s) - g_posdot[i] * ESC) : 0.0f;
    #pragma unroll
    for (int o = 16; o > 0; o >>= 1) local += __shfl_xor_sync(0xffffffffu, local, o);

    __shared__ float ws[8];
    if ((tid & 31) == 0) ws[tid >> 5] = local;
    __syncthreads();
    if (tid == 0) {
        float v = 0.0f;
        #pragma unroll
        for (int w = 0; w < 8; w++) v += ws[w];
        g_blk[blockIdx.x] = v;
        __threadfence();
        unsigned int tkt = atomicAdd(&g_cnt, 1u);
        if (tkt == 127u) {
            __threadfence();
            float tot = 0.0f;
            #pragma unroll 16
            for (int k = 0; k < 128; k++) tot += g_blk[k];
            out[0] = tot / (float)N;
            g_cnt = 0u;   // reset for next graph replay
        }
    }
}

// ---------------------------------------------------------------------------
extern "C" void kernel_launch(void* const* d_in, const int* in_sizes, int n_in,
                              void* d_out, int out_size) {
    const float* features = (const float*)d_in[0];
    float* out = (float*)d_out;

    static bool attr_set = false;
    if (!attr_set) {
        cudaFuncSetAttribute(simlse_mma, cudaFuncAttributeMaxDynamicSharedMemorySize,
                             SMEM_TOTAL);
        attr_set = true;
    }

    simlse_mma<<<NTILE, 256, SMEM_TOTAL>>>(features);
    finalize_kernel<<<128, 256>>>(out);
}

// round 9
// speedup vs baseline: 1.1614x; 1.1614x over previous
#include <cuda_runtime.h>
#include <cuda_bf16.h>
#include <math.h>
#include <stdint.h>

#define N 8192
#define D 256
#define INVT (1.0f / 0.07f)
#define KC 64
#define NB 64                       // 8192/128 blocks per dim
#define NTILE (NB * (NB + 1) / 2)   // 2080 upper-triangular tiles

__device__ __align__(16) __nv_bfloat16 g_fbf16[N * D];  // 4MB normalized bf16
__device__ float g_rowpart[NB * N];   // [cb][i]  2MB
__device__ float g_colpart[NB * N];   // [rb][j]  2MB
__device__ float g_posdot[N];
__device__ float g_blk[64];
__device__ unsigned int g_cnt;

// smem layout: A 2x16KB, B 2x16KB, then reduce buffers
#define SM_ROW  65536                 // float[128][2]  (1KB)
#define SM_COL  (65536 + 1024)        // float[128][4]  (2KB)
#define SMEM_TOTAL (65536 + 1024 + 2048)

// ---------------------------------------------------------------------------
__device__ __forceinline__ uint32_t smem_u32(const void* p) {
    uint32_t a;
    asm("{ .reg .u64 t; cvta.to.shared.u64 t, %1; cvt.u32.u64 %0, t; }" : "=r"(a) : "l"(p));
    return a;
}
#define SW128(o) ((o) ^ (((o) >> 3) & 0x70))

__device__ __forceinline__ void cpasync16(uint32_t s, const void* g) {
    asm volatile("cp.async.cg.shared.global [%0], [%1], 16;" :: "r"(s), "l"(g));
}
#define CP_COMMIT() asm volatile("cp.async.commit_group;" ::: "memory")
#define CP_WAIT(n)  asm volatile("cp.async.wait_group %0;" :: "n"(n) : "memory")

__device__ __forceinline__ void ldsm_x4(uint32_t& r0, uint32_t& r1, uint32_t& r2,
                                        uint32_t& r3, uint32_t a) {
    asm volatile("ldmatrix.sync.aligned.m8n8.x4.shared.b16 {%0,%1,%2,%3}, [%4];"
        : "=r"(r0), "=r"(r1), "=r"(r2), "=r"(r3) : "r"(a));
}
__device__ __forceinline__ void mma16816(float* c, const uint32_t* a,
                                         uint32_t b0, uint32_t b1) {
    asm volatile(
        "mma.sync.aligned.m16n8k16.row.col.f32.bf16.bf16.f32 "
        "{%0,%1,%2,%3},{%4,%5,%6,%7},{%8,%9},{%0,%1,%2,%3};"
        : "+f"(c[0]), "+f"(c[1]), "+f"(c[2]), "+f"(c[3])
        : "r"(a[0]), "r"(a[1]), "r"(a[2]), "r"(a[3]), "r"(b0), "r"(b1));
}

// ---------------------------------------------------------------------------
// Kernel 1: row L2-normalize -> bf16. 4 rows per warp (MLP=8).
// ---------------------------------------------------------------------------
__global__ void normalize_kernel(const float* __restrict__ x) {
    const int warp = threadIdx.x >> 5;
    const int lane = threadIdx.x & 31;
    const int row0 = blockIdx.x * 32 + warp * 4;

    float4 v[4][2];
    #pragma unroll
    for (int r = 0; r < 4; r++) {
        const float* xr = x + (size_t)(row0 + r) * D + lane * 8;
        v[r][0] = *(const float4*)xr;
        v[r][1] = *(const float4*)(xr + 4);
    }

    float s[4];
    #pragma unroll
    for (int r = 0; r < 4; r++) {
        s[r] = v[r][0].x*v[r][0].x + v[r][0].y*v[r][0].y +
               v[r][0].z*v[r][0].z + v[r][0].w*v[r][0].w +
               v[r][1].x*v[r][1].x + v[r][1].y*v[r][1].y +
               v[r][1].z*v[r][1].z + v[r][1].w*v[r][1].w;
    }
    #pragma unroll
    for (int o = 16; o > 0; o >>= 1) {
        #pragma unroll
        for (int r = 0; r < 4; r++) s[r] += __shfl_xor_sync(0xffffffffu, s[r], o);
    }

    #pragma unroll
    for (int r = 0; r < 4; r++) {
        const float rn = 1.0f / fmaxf(sqrtf(s[r]), 1e-8f);
        __nv_bfloat162 p[4];
        p[0] = __floats2bfloat162_rn(v[r][0].x*rn, v[r][0].y*rn);
        p[1] = __floats2bfloat162_rn(v[r][0].z*rn, v[r][0].w*rn);
        p[2] = __floats2bfloat162_rn(v[r][1].x*rn, v[r][1].y*rn);
        p[3] = __floats2bfloat162_rn(v[r][1].z*rn, v[r][1].w*rn);
        *(uint4*)(g_fbf16 + (size_t)(row0 + r) * D + lane * 8) = *(uint4*)p;
    }
}

// ---------------------------------------------------------------------------
// Kernel 2: HMMA fused sim GEMM, upper-triangular tiles (identical to R6).
// ---------------------------------------------------------------------------
__global__ __launch_bounds__(256, 2) void simlse_mma() {
    extern __shared__ __align__(1024) char smem[];
    const uint32_t sA0 = smem_u32(smem);
    const uint32_t sB0 = sA0 + 2 * 16384;
    float* sm_row = (float*)(smem + SM_ROW);   // [128][2]
    float* sm_col = (float*)(smem + SM_COL);   // [128][4]

    // triangular tile map
    int t = blockIdx.x, rb = 0, base = 0;
    while (base + (NB - rb) <= t) { base += NB - rb; rb++; }
    const int cb = rb + (t - base);
    const bool diag = (rb == cb);

    const int tid  = threadIdx.x;
    const int lane = tid & 31;
    const int wm   = (tid >> 5) >> 1;
    const int wn   = (tid >> 5) & 1;
    const int i0   = rb * 128;
    const int j0   = cb * 128;

    const int sel = lane >> 3;
    const int sub = lane & 7;
    const int g   = lane >> 2;
    const int q   = lane & 3;

    float c[2][8][4];
    #pragma unroll
    for (int mf = 0; mf < 2; mf++)
        #pragma unroll
        for (int nf = 0; nf < 8; nf++)
            #pragma unroll
            for (int e = 0; e < 4; e++) c[mf][nf][e] = 0.0f;

    auto load_chunk = [&](int kc, int bf) {
        const __nv_bfloat16* gA = g_fbf16 + (size_t)i0 * D + kc * KC;
        const __nv_bfloat16* gB = g_fbf16 + (size_t)j0 * D + kc * KC;
        const uint32_t dA = sA0 + bf * 16384;
        const uint32_t dB = sB0 + bf * 16384;
        #pragma unroll
        for (int v = 0; v < 4; v++) {
            int idx = tid + 256 * v;
            int r   = idx >> 3;
            int ci  = idx & 7;
            uint32_t so = SW128(r * 128 + ci * 16);
            cpasync16(dA + so, gA + (size_t)r * D + ci * 8);
            if (!diag) cpasync16(dB + so, gB + (size_t)r * D + ci * 8);
        }
    };

    load_chunk(0, 0);
    CP_COMMIT();

    const uint32_t sBbase = diag ? sA0 : sB0;

    float rs[2][2] = {{0.0f, 0.0f}, {0.0f, 0.0f}};

    auto load_a = [&](uint32_t bA, int ks, uint32_t a[2][4]) {
        #pragma unroll
        for (int mf = 0; mf < 2; mf++) {
            int row = wm * 32 + mf * 16 + (sel & 1) * 8 + sub;
            uint32_t off = (uint32_t)(row * 128 + ks * 32 + (sel >> 1) * 16);
            ldsm_x4(a[mf][0], a[mf][1], a[mf][2], a[mf][3], bA + SW128(off));
        }
    };
    auto load_b = [&](uint32_t bB, int ks, uint32_t b[4][4]) {
        #pragma unroll
        for (int p = 0; p < 4; p++) {
            int n = wn * 64 + p * 16 + (sel >> 1) * 8 + sub;
            uint32_t off = (uint32_t)(n * 128 + ks * 32 + (sel & 1) * 16);
            ldsm_x4(b[p][0], b[p][1], b[p][2], b[p][3], bB + SW128(off));
        }
    };

    for (int kc = 0; kc < 3; kc++) {
        CP_WAIT(0);
        __syncthreads();
        load_chunk(kc + 1, (kc + 1) & 1);
        CP_COMMIT();

        const uint32_t bA = sA0 + (kc & 1) * 16384;
        const uint32_t bB = sBbase + (kc & 1) * 16384;

        #pragma unroll
        for (int ks = 0; ks < 4; ks++) {
            uint32_t a[2][4], b[4][4];
            load_a(bA, ks, a);
            load_b(bB, ks, b);
            #pragma unroll
            for (int p = 0; p < 4; p++)
                #pragma unroll
                for (int mf = 0; mf < 2; mf++) {
                    mma16816(c[mf][2 * p],     a[mf], b[p][0], b[p][1]);
                    mma16816(c[mf][2 * p + 1], a[mf], b[p][2], b[p][3]);
                }
        }
    }

    CP_WAIT(0);
    __syncthreads();
    {
        const uint32_t bA = sA0 + 16384;
        const uint32_t bB = sBbase + 16384;

        #pragma unroll
        for (int ks = 0; ks < 3; ks++) {
            uint32_t a[2][4], b[4][4];
            load_a(bA, ks, a);
            load_b(bB, ks, b);
            #pragma unroll
            for (int p = 0; p < 4; p++)
                #pragma unroll
                for (int mf = 0; mf < 2; mf++) {
                    mma16816(c[mf][2 * p],     a[mf], b[p][0], b[p][1]);
                    mma16816(c[mf][2 * p + 1], a[mf], b[p][2], b[p][3]);
                }
        }

        // ks == 3: per nf, finish MMA then immediately run that nf's epilogue.
        uint32_t a[2][4], b[4][4];
        load_a(bA, 3, a);
        load_b(bB, 3, b);
        #pragma unroll
        for (int p = 0; p < 4; p++) {
            #pragma unroll
            for (int half = 0; half < 2; half++) {
                const int nf = 2 * p + half;
                mma16816(c[0][nf], a[0], b[p][2 * half], b[p][2 * half + 1]);
                mma16816(c[1][nf], a[1], b[p][2 * half], b[p][2 * half + 1]);

                float s0 = 0.0f, s1 = 0.0f;
                const int jb = j0 + wn * 64 + nf * 8 + 2 * q;
                #pragma unroll
                for (int mf = 0; mf < 2; mf++) {
                    #pragma unroll
                    for (int h = 0; h < 2; h++) {
                        const int i  = i0 + wm * 32 + mf * 16 + 8 * h + g;
                        const int pc = (i + N / 2) & (N - 1);
                        const float v0 = c[mf][nf][h * 2 + 0];
                        const float v1 = c[mf][nf][h * 2 + 1];
                        if (jb == pc)     { g_posdot[i] = v0; g_posdot[jb] = v0; }
                        if (jb + 1 == pc) { g_posdot[i] = v1; g_posdot[jb + 1] = v1; }
                        const float e0 = (jb != i)     ? __expf(v0 * INVT) : 0.0f;
                        const float e1 = (jb + 1 != i) ? __expf(v1 * INVT) : 0.0f;
                        rs[mf][h] += e0 + e1;
                        s0 += e0;
                        s1 += e1;
                    }
                }
                s0 += __shfl_xor_sync(0xffffffffu, s0, 4);
                s0 += __shfl_xor_sync(0xffffffffu, s0, 8);
                s0 += __shfl_xor_sync(0xffffffffu, s0, 16);
                s1 += __shfl_xor_sync(0xffffffffu, s1, 4);
                s1 += __shfl_xor_sync(0xffffffffu, s1, 8);
                s1 += __shfl_xor_sync(0xffffffffu, s1, 16);
                if (g == nf) {
                    const int jl = wn * 64 + nf * 8 + 2 * q;
                    sm_col[jl * 4 + wm]       = s0;
                    sm_col[(jl + 1) * 4 + wm] = s1;
                }
            }
        }
    }

    #pragma unroll
    for (int mf = 0; mf < 2; mf++) {
        #pragma unroll
        for (int h = 0; h < 2; h++) {
            float v = rs[mf][h];
            v += __shfl_xor_sync(0xffffffffu, v, 1);
            v += __shfl_xor_sync(0xffffffffu, v, 2);
            if (q == 0) {
                const int il = wm * 32 + mf * 16 + 8 * h + g;
                sm_row[il * 2 + wn] = v;
            }
        }
    }
    __syncthreads();

    if (tid < 128) {
        g_rowpart[(size_t)cb * N + i0 + tid] = sm_row[tid * 2] + sm_row[tid * 2 + 1];
    } else if (!diag) {
        const int j = tid - 128;
        g_colpart[(size_t)rb * N + j0 + j] =
            sm_col[j * 4] + sm_col[j * 4 + 1] + sm_col[j * 4 + 2] + sm_col[j * 4 + 3];
    }
}

// ---------------------------------------------------------------------------
// Kernel 3: per-row nll, coalesced. 64 blocks x 256 threads.
// thread (r = tid&127, s = tid>>7): sums 64 slices of rowpart (s=0) or
// colpart (s=1) for row i = blk*128 + r; consecutive lanes -> consecutive i.
// ---------------------------------------------------------------------------
__global__ void finalize_kernel(float* __restrict__ out) {
    const int tid = threadIdx.x;
    const int r   = tid & 127;
    const int s   = tid >> 7;
    const int i   = blockIdx.x * 128 + r;

    const float* basep = s ? g_colpart : g_rowpart;
    float acc = 0.0f;
    #pragma unroll 8
    for (int sp = 0; sp < NB; sp++) acc += basep[(size_t)sp * N + i];

    __shared__ float sm[256];
    sm[tid] = acc;
    __syncthreads();

    float local = 0.0f;
    if (tid < 128) {
        const float tot = sm[tid] + sm[tid + 128];
        local = logf(tot) - g_posdot[i] * INVT;
    }
    #pragma unroll
    for (int o = 16; o > 0; o >>= 1) local += __shfl_xor_sync(0xffffffffu, local, o);

    __shared__ float ws[8];
    if ((tid & 31) == 0) ws[tid >> 5] = local;
    __syncthreads();
    if (tid == 0) {
        float v = ws[0] + ws[1] + ws[2] + ws[3];
        g_blk[blockIdx.x] = v;
        __threadfence();
        unsigned int tkt = atomicAdd(&g_cnt, 1u);
        if (tkt == 63u) {
            __threadfence();
            float tot = 0.0f;
            #pragma unroll 16
            for (int k = 0; k < 64; k++) tot += g_blk[k];
            out[0] = tot / (float)N;
            g_cnt = 0u;   // reset for next graph replay
        }
    }
}

// ---------------------------------------------------------------------------
extern "C" void kernel_launch(void* const* d_in, const int* in_sizes, int n_in,
                              void* d_out, int out_size) {
    const float* features = (const float*)d_in[0];
    float* out = (float*)d_out;

    static bool attr_set = false;
    if (!attr_set) {
        cudaFuncSetAttribute(simlse_mma, cudaFuncAttributeMaxDynamicSharedMemorySize,
                             SMEM_TOTAL);
        attr_set = true;
    }

    normalize_kernel<<<N / 32, 256>>>(features);
    simlse_mma<<<NTILE, 256, SMEM_TOTAL>>>();
    finalize_kernel<<<64, 256>>>(out);
}